// round 2
// baseline (speedup 1.0000x reference)
#include <cuda_runtime.h>

// Problem constants
#define NB 8
#define NC 256
#define NN 1024
#define NT 3

// Scratch: projected Q (student) and K/V (teachers), layout [.., C, N] (c-major)
__device__ float g_Qp[NB * NC * NN];            // 8 MB
__device__ float g_Kp[NT * NB * NC * NN];       // 24 MB
__device__ float g_Vp[NT * NB * NC * NN];       // 24 MB

// ---------------------------------------------------------------------------
// Projection kernel: dst[o][n] = sum_c W[o][c] * X[c][n] + bias[o]
// Grid: (N/64, C/64, 7*8).  z = proj*8 + b.  proj: 0=Q(student), 1..3=K(t), 4..6=V(t)
// ---------------------------------------------------------------------------
__global__ __launch_bounds__(256) void proj_kernel(
    const float* __restrict__ Wq, const float* __restrict__ bq,
    const float* __restrict__ Wk, const float* __restrict__ bk,
    const float* __restrict__ Wv, const float* __restrict__ bv,
    const float* __restrict__ xs, const float* __restrict__ x0,
    const float* __restrict__ x1, const float* __restrict__ x2)
{
    __shared__ float Ws[64 * 16];   // [o][cc], stride 16
    __shared__ float Xs[16 * 64];   // [cc][n], stride 64

    const int tid = threadIdx.x;
    const int tx = tid & 15, ty = tid >> 4;
    const int n0 = blockIdx.x * 64;
    const int o0 = blockIdx.y * 64;
    const int z  = blockIdx.z;
    const int p  = z >> 3, b = z & 7;

    const float* W;
    const float* bias;
    const float* X;
    float* dst;
    if (p == 0) {
        W = Wq; bias = bq; X = xs + b * NC * NN; dst = g_Qp + b * NC * NN;
    } else if (p <= 3) {
        W = Wk; bias = bk;
        const float* tf = (p == 1) ? x0 : ((p == 2) ? x1 : x2);
        X = tf + b * NC * NN; dst = g_Kp + ((p - 1) * NB + b) * NC * NN;
    } else {
        W = Wv; bias = bv;
        const float* tf = (p == 4) ? x0 : ((p == 5) ? x1 : x2);
        X = tf + b * NC * NN; dst = g_Vp + ((p - 4) * NB + b) * NC * NN;
    }

    float acc[4][4];
#pragma unroll
    for (int i = 0; i < 4; i++)
#pragma unroll
        for (int j = 0; j < 4; j++) acc[i][j] = 0.0f;

    for (int kk = 0; kk < NC; kk += 16) {
        __syncthreads();
        {   // W tile 64x16, natural layout (broadcast reads later)
            int o_l = tid >> 2, cg = tid & 3;
            float4 w4 = *(const float4*)&W[(o0 + o_l) * NC + kk + cg * 4];
            *(float4*)&Ws[o_l * 16 + cg * 4] = w4;
        }
        {   // X tile 16x64
            int cc = tid >> 4, ng = tid & 15;
            float4 x4 = *(const float4*)&X[(kk + cc) * NN + n0 + ng * 4];
            *(float4*)&Xs[cc * 64 + ng * 4] = x4;
        }
        __syncthreads();
#pragma unroll
        for (int c4 = 0; c4 < 16; c4 += 4) {
            float4 a4[4], b4[4];
#pragma unroll
            for (int i = 0; i < 4; i++)
                a4[i] = *(const float4*)&Ws[(ty + 16 * i) * 16 + c4];
#pragma unroll
            for (int e = 0; e < 4; e++)
                b4[e] = *(const float4*)&Xs[(c4 + e) * 64 + tx * 4];
#pragma unroll
            for (int i = 0; i < 4; i++) {
                const float* qa = (const float*)&a4[i];
#pragma unroll
                for (int e = 0; e < 4; e++) {
                    const float* bb = (const float*)&b4[e];
                    float a = qa[e];
                    acc[i][0] += a * bb[0];
                    acc[i][1] += a * bb[1];
                    acc[i][2] += a * bb[2];
                    acc[i][3] += a * bb[3];
                }
            }
        }
    }

#pragma unroll
    for (int i = 0; i < 4; i++) {
        float bi = bias[o0 + ty + 16 * i];
        float4 r;
        r.x = acc[i][0] + bi; r.y = acc[i][1] + bi;
        r.z = acc[i][2] + bi; r.w = acc[i][3] + bi;
        *(float4*)&dst[(o0 + ty + 16 * i) * NN + n0 + tx * 4] = r;
    }
}

// ---------------------------------------------------------------------------
// Fused flash-attention over 3 teachers + residual + 1/3 average.
// Grid: 128 blocks = B(8) x qtiles(16). Block = 256 threads (16x16).
// Thread micro-tiles: S: q=ty+16i (i<4), m=4tx+j (j<4)
//                     O: q=ty+16i, c=4tx+j+64g (g<4)
// ---------------------------------------------------------------------------
#define QSTR 260
#define KSTR 64
#define VSTR 260
#define PSTR 68
#define SSTR 65

__global__ __launch_bounds__(256, 1) void attn_kernel(
    const float* __restrict__ student, float* __restrict__ out)
{
    extern __shared__ float sm[];
    float* Qqs = sm;                   // 64 x 260  [q][c]
    float* Kcs = Qqs + 64 * QSTR;      // 256 x 64  [c][m]
    float* Vts = Kcs + 256 * KSTR;     // 64 x 260  [m][c]  (reused as stage 256x65)
    float* Psm = Vts + 64 * VSTR;      // 64 x 68   [q][m]

    const int tid = threadIdx.x;
    const int tx = tid & 15, ty = tid >> 4;
    const int b  = blockIdx.x >> 4;
    const int n0 = (blockIdx.x & 15) * 64;

    // Load Q tile transposed: Qqs[q][c] = Qp[b][c][n0+q]
    const float* Qb = g_Qp + b * NC * NN;
    for (int r = 0; r < 64; r++) {
        int idx = tid + 256 * r;
        int c = idx >> 6, q = idx & 63;
        Qqs[q * QSTR + c] = Qb[c * NN + n0 + q];
    }

    const float* stu = student + b * NC * NN;
    float* outb = out + b * NC * NN;

    for (int t = 0; t < NT; t++) {
        const float* Kb = g_Kp + (t * NB + b) * NC * NN;
        const float* Vb = g_Vp + (t * NB + b) * NC * NN;

        float oacc[4][4][4];
#pragma unroll
        for (int i = 0; i < 4; i++)
#pragma unroll
            for (int g = 0; g < 4; g++)
#pragma unroll
                for (int j = 0; j < 4; j++) oacc[i][g][j] = 0.0f;
        float mrun[4] = {-1e30f, -1e30f, -1e30f, -1e30f};
        float lrun[4] = {0.0f, 0.0f, 0.0f, 0.0f};

        for (int m0 = 0; m0 < NN; m0 += 64) {
            __syncthreads();
            // K tile: Kcs[c][m] = Kb[c][m0+m] (vectorized, conflict-free)
            for (int r = 0; r < 16; r++) {
                int idx = tid + 256 * r;
                int c = idx >> 4, mq = idx & 15;
                float4 k4 = *(const float4*)&Kb[c * NN + m0 + mq * 4];
                *(float4*)&Kcs[c * KSTR + mq * 4] = k4;
            }
            // V tile transposed: Vts[m][c] = Vb[c][m0+m]
            for (int r = 0; r < 64; r++) {
                int idx = tid + 256 * r;
                int c = idx >> 6, m = idx & 63;
                Vts[m * VSTR + c] = Vb[c * NN + m0 + m];
            }
            __syncthreads();

            // S = Q K^T  (scaled later)
            float s[4][4];
#pragma unroll
            for (int i = 0; i < 4; i++)
#pragma unroll
                for (int j = 0; j < 4; j++) s[i][j] = 0.0f;

#pragma unroll 8
            for (int c4 = 0; c4 < NC; c4 += 4) {
                float4 qa4[4], kb4[4];
#pragma unroll
                for (int i = 0; i < 4; i++)
                    qa4[i] = *(const float4*)&Qqs[(ty + 16 * i) * QSTR + c4];
#pragma unroll
                for (int e = 0; e < 4; e++)
                    kb4[e] = *(const float4*)&Kcs[(c4 + e) * KSTR + tx * 4];
#pragma unroll
                for (int i = 0; i < 4; i++) {
                    const float* qa = (const float*)&qa4[i];
#pragma unroll
                    for (int e = 0; e < 4; e++) {
                        const float* kb = (const float*)&kb4[e];
                        float a = qa[e];
                        s[i][0] += a * kb[0];
                        s[i][1] += a * kb[1];
                        s[i][2] += a * kb[2];
                        s[i][3] += a * kb[3];
                    }
                }
            }

            // Online softmax (scale = C^-0.5 = 1/16)
            float newm[4], alpha[4];
#pragma unroll
            for (int i = 0; i < 4; i++) {
                float tm = fmaxf(fmaxf(s[i][0], s[i][1]), fmaxf(s[i][2], s[i][3])) * 0.0625f;
#pragma unroll
                for (int d = 1; d < 16; d <<= 1)
                    tm = fmaxf(tm, __shfl_xor_sync(0xffffffffu, tm, d));
                newm[i]  = fmaxf(mrun[i], tm);
                alpha[i] = __expf(mrun[i] - newm[i]);
                mrun[i]  = newm[i];
            }
            float p[4][4];
#pragma unroll
            for (int i = 0; i < 4; i++) {
                float ts = 0.0f;
#pragma unroll
                for (int j = 0; j < 4; j++) {
                    p[i][j] = __expf(s[i][j] * 0.0625f - newm[i]);
                    ts += p[i][j];
                }
#pragma unroll
                for (int d = 1; d < 16; d <<= 1)
                    ts += __shfl_xor_sync(0xffffffffu, ts, d);
                lrun[i] = lrun[i] * alpha[i] + ts;
            }
            // store P tile
#pragma unroll
            for (int i = 0; i < 4; i++) {
                float4 pr;
                pr.x = p[i][0]; pr.y = p[i][1]; pr.z = p[i][2]; pr.w = p[i][3];
                *(float4*)&Psm[(ty + 16 * i) * PSTR + tx * 4] = pr;
            }
            // rescale running output
#pragma unroll
            for (int i = 0; i < 4; i++) {
                float a = alpha[i];
#pragma unroll
                for (int g = 0; g < 4; g++)
#pragma unroll
                    for (int j = 0; j < 4; j++) oacc[i][g][j] *= a;
            }
            __syncthreads();

            // O += P * V
#pragma unroll 8
            for (int m = 0; m < 64; m++) {
                float pv[4];
#pragma unroll
                for (int i = 0; i < 4; i++)
                    pv[i] = Psm[(ty + 16 * i) * PSTR + m];
                float4 vv[4];
#pragma unroll
                for (int g = 0; g < 4; g++)
                    vv[g] = *(const float4*)&Vts[m * VSTR + tx * 4 + 64 * g];
#pragma unroll
                for (int i = 0; i < 4; i++) {
                    float a = pv[i];
#pragma unroll
                    for (int g = 0; g < 4; g++) {
                        const float* vf = (const float*)&vv[g];
                        oacc[i][g][0] += a * vf[0];
                        oacc[i][g][1] += a * vf[1];
                        oacc[i][g][2] += a * vf[2];
                        oacc[i][g][3] += a * vf[3];
                    }
                }
            }
        } // key tiles

        // Per-teacher epilogue: out += oacc / (3*l), coalesced via smem transpose
        __syncthreads();
        float* stage = Vts;   // 256 x 65 [c][q]
#pragma unroll
        for (int i = 0; i < 4; i++) {
            float inv = 1.0f / (3.0f * lrun[i]);
            int q = ty + 16 * i;
#pragma unroll
            for (int g = 0; g < 4; g++)
#pragma unroll
                for (int j = 0; j < 4; j++) {
                    int c = tx * 4 + j + 64 * g;
                    stage[c * SSTR + q] = oacc[i][g][j] * inv;
                }
        }
        __syncthreads();
        for (int r = 0; r < 64; r++) {
            int idx = tid + 256 * r;
            int c = idx >> 6, n = idx & 63;
            int off = c * NN + n0 + n;
            float base = (t == 0) ? stu[off] : outb[off];
            outb[off] = base + stage[c * SSTR + n];
        }
        __syncthreads();
    } // teachers
}

// ---------------------------------------------------------------------------
extern "C" void kernel_launch(void* const* d_in, const int* in_sizes, int n_in,
                              void* d_out, int out_size)
{
    const float* student = (const float*)d_in[0];
    const float* t0 = (const float*)d_in[1];
    const float* t1 = (const float*)d_in[2];
    const float* t2 = (const float*)d_in[3];
    const float* Wq = (const float*)d_in[4];
    const float* bq = (const float*)d_in[5];
    const float* Wk = (const float*)d_in[6];
    const float* bk = (const float*)d_in[7];
    const float* Wv = (const float*)d_in[8];
    const float* bv = (const float*)d_in[9];
    float* out = (float*)d_out;

    dim3 pg(NN / 64, NC / 64, 7 * NB);
    proj_kernel<<<pg, 256>>>(Wq, bq, Wk, bk, Wv, bv, student, t0, t1, t2);

    const int smem_bytes = (64 * QSTR + 256 * KSTR + 64 * VSTR + 64 * PSTR) * 4;
    cudaFuncSetAttribute(attn_kernel, cudaFuncAttributeMaxDynamicSharedMemorySize,
                         smem_bytes);
    attn_kernel<<<NB * (NN / 64), 256, smem_bytes>>>(student, out);
}